// round 15
// baseline (speedup 1.0000x reference)
#include <cuda_runtime.h>

#define BATCH 2048
#define IN_F  256
#define OUT_F 256
#define DEG   8

// ---------------- device scratch (no allocation allowed) ----------------
__device__ unsigned int g_min_enc;
__device__ unsigned int g_max_enc;
__device__ float g_base[BATCH * OUT_F];   // 2 MiB, L2-resident

// Monotonic float<->uint encoding for atomic min/max
__device__ __forceinline__ unsigned int enc_f(float f) {
    unsigned int i = __float_as_uint(f);
    return (i & 0x80000000u) ? ~i : (i | 0x80000000u);
}
__device__ __forceinline__ float dec_f(unsigned int u) {
    unsigned int i = (u & 0x80000000u) ? (u & 0x7fffffffu) : ~u;
    return __uint_as_float(i);
}

// ---------------- kernel 0: reset reduction state (determinism) ----------
__global__ void k_init() {
    g_min_enc = 0xFFFFFFFFu;  // encodes +inf side
    g_max_enc = 0x00000000u;  // encodes -inf side
}

// ---------------- kernel 1: global min/max of x ---------------------------
__global__ void k_minmax(const float* __restrict__ x, int n4) {
    const float4* x4 = (const float4*)x;
    int idx    = blockIdx.x * blockDim.x + threadIdx.x;
    int stride = gridDim.x * blockDim.x;
    float lmin =  3.402823466e38f;
    float lmax = -3.402823466e38f;
    for (int k = idx; k < n4; k += stride) {
        float4 v = x4[k];
        lmin = fminf(lmin, fminf(fminf(v.x, v.y), fminf(v.z, v.w)));
        lmax = fmaxf(lmax, fmaxf(fmaxf(v.x, v.y), fmaxf(v.z, v.w)));
    }
    #pragma unroll
    for (int off = 16; off; off >>= 1) {
        lmin = fminf(lmin, __shfl_xor_sync(0xffffffffu, lmin, off));
        lmax = fmaxf(lmax, __shfl_xor_sync(0xffffffffu, lmax, off));
    }
    __shared__ float smin[8], smax[8];
    int wid = threadIdx.x >> 5, lid = threadIdx.x & 31;
    if (lid == 0) { smin[wid] = lmin; smax[wid] = lmax; }
    __syncthreads();
    if (threadIdx.x == 0) {
        float m = smin[0], M = smax[0];
        #pragma unroll
        for (int w = 1; w < 8; w++) { m = fminf(m, smin[w]); M = fmaxf(M, smax[w]); }
        atomicMin(&g_min_enc, enc_f(m));
        atomicMax(&g_max_enc, enc_f(M));
    }
}

// ---------------- kernel 2: base_out = swish(x) @ W_base ------------------
// Block handles 16 batch rows x all 256 outputs. Thread = one output column,
// 16 accumulators, rank-1 updates over k with x staged (transposed) in smem.
__global__ __launch_bounds__(256) void k_base_gemm(const float* __restrict__ x,
                                                   const float* __restrict__ Wb) {
    __shared__ __align__(16) float sxT[IN_F][16];   // [k][b_local], 16 KiB
    const int b0  = blockIdx.x * 16;
    const int tid = threadIdx.x;

    // load x rows, apply swish, store transposed
    for (int idx = tid; idx < 16 * IN_F; idx += 256) {
        int bl = idx >> 8;            // idx / 256
        int k  = idx & (IN_F - 1);    // idx % 256   (coalesced global read)
        float v = x[(b0 + bl) * IN_F + k];
        float s = v / (1.0f + __expf(-v));
        sxT[k][bl] = s;
    }
    __syncthreads();

    float acc[16];
    #pragma unroll
    for (int i = 0; i < 16; i++) acc[i] = 0.0f;

    const int o = tid;
    #pragma unroll 4
    for (int k = 0; k < IN_F; k++) {
        float w = Wb[k * OUT_F + o];
        const float4* sr = (const float4*)&sxT[k][0];
        float4 s0 = sr[0], s1 = sr[1], s2 = sr[2], s3 = sr[3];
        acc[0]  += s0.x * w;  acc[1]  += s0.y * w;  acc[2]  += s0.z * w;  acc[3]  += s0.w * w;
        acc[4]  += s1.x * w;  acc[5]  += s1.y * w;  acc[6]  += s1.z * w;  acc[7]  += s1.w * w;
        acc[8]  += s2.x * w;  acc[9]  += s2.y * w;  acc[10] += s2.z * w;  acc[11] += s2.w * w;
        acc[12] += s3.x * w;  acc[13] += s3.y * w;  acc[14] += s3.z * w;  acc[15] += s3.w * w;
    }
    #pragma unroll
    for (int bl = 0; bl < 16; bl++)
        g_base[(b0 + bl) * OUT_F + o] = acc[bl];
}

// ---------------- kernel 3: main fused output ------------------------------
// Grid: (IN_F/IPB, BATCH/BPB). Block = 256 threads:
//   i_local = tid>>6 (4 input-feature channels per block)
//   oq      = tid&63 (one float4 of the output row: o = 4*oq)
// Each thread holds its 4x8 slice of cheb_weight in REGISTERS (loaded once),
// then streams 64 batch rows: 1 broadcast x-load, Chebyshev recurrence,
// 1 LDG.128 of base (L2 hit), 32 FMA, 1 STG.128.
#define IPB 4
#define BPB 64
__global__ __launch_bounds__(256, 2) void k_cheb_main(const float* __restrict__ x,
                                                      const float* __restrict__ Wc,
                                                      float* __restrict__ out) {
    const int tid = threadIdx.x;
    const int il  = tid >> 6;       // 0..3
    const int oq  = tid & 63;       // 0..63
    const int i   = blockIdx.x * IPB + il;
    const int b0  = blockIdx.y * BPB;

    // --- load this thread's 32 cheb weights into registers ---
    // memory layout: Wc[i][o][d], element e of the 32-float run = (o=4oq+(e>>3), d=e&7)
    const float4* wp = (const float4*)(Wc + (size_t)i * (OUT_F * DEG) + oq * 32);
    float wr[4][8];
    #pragma unroll
    for (int q = 0; q < 8; q++) {
        float4 v = wp[q];
        int j = q >> 1;
        int db = (q & 1) * 4;
        wr[j][db + 0] = v.x; wr[j][db + 1] = v.y;
        wr[j][db + 2] = v.z; wr[j][db + 3] = v.w;
    }

    const float xmin  = dec_f(g_min_enc);
    const float xmax  = dec_f(g_max_enc);
    const float scale = 2.0f / (xmax - xmin);

    const float4* basep = (const float4*)g_base;
    float4* outp = (float4*)out;

    #pragma unroll 2
    for (int bb = 0; bb < BPB; bb++) {
        const int b = b0 + bb;
        float xv = __ldg(&x[b * IN_F + i]);               // warp-broadcast
        float xs = (xv - xmin) * scale - 1.0f;
        float T[8];
        T[0] = 1.0f; T[1] = xs;
        float xs2 = xs + xs;
        #pragma unroll
        for (int d = 2; d < 8; d++) T[d] = xs2 * T[d - 1] - T[d - 2];

        float4 r = basep[b * (OUT_F / 4) + oq];           // L2/L1 hit
        #pragma unroll
        for (int d = 0; d < 8; d++) {
            r.x += T[d] * wr[0][d];
            r.y += T[d] * wr[1][d];
            r.z += T[d] * wr[2][d];
            r.w += T[d] * wr[3][d];
        }
        outp[(size_t)(b * IN_F + i) * (OUT_F / 4) + oq] = r;   // 512B/warp burst
    }
}

// ---------------- launch ----------------------------------------------------
extern "C" void kernel_launch(void* const* d_in, const int* in_sizes, int n_in,
                              void* d_out, int out_size) {
    (void)in_sizes; (void)n_in; (void)out_size;
    const float* x  = (const float*)d_in[0];   // (2048, 256)
    const float* Wb = (const float*)d_in[1];   // (256, 256)
    const float* Wc = (const float*)d_in[2];   // (256, 256, 8)
    float* out = (float*)d_out;                // (2048, 256, 256)

    k_init<<<1, 1>>>();
    k_minmax<<<128, 256>>>(x, (BATCH * IN_F) / 4);
    k_base_gemm<<<BATCH / 16, 256>>>(x, Wb);
    k_cheb_main<<<dim3(IN_F / IPB, BATCH / BPB), 256>>>(x, Wc, out);
}

// round 16
// speedup vs baseline: 1.0202x; 1.0202x over previous
#include <cuda_runtime.h>

#define BATCH 2048
#define IN_F  256
#define OUT_F 256
#define DEG   8

// ---------------- device scratch (no allocation allowed) ----------------
__device__ unsigned int g_min_enc;
__device__ unsigned int g_max_enc;
__device__ float g_base[BATCH * OUT_F];   // 2 MiB, L2-resident

// Monotonic float<->uint encoding for atomic min/max
__device__ __forceinline__ unsigned int enc_f(float f) {
    unsigned int i = __float_as_uint(f);
    return (i & 0x80000000u) ? ~i : (i | 0x80000000u);
}
__device__ __forceinline__ float dec_f(unsigned int u) {
    unsigned int i = (u & 0x80000000u) ? (u & 0x7fffffffu) : ~u;
    return __uint_as_float(i);
}

// ---------------- kernel 0: reset reduction state (determinism) ----------
__global__ void k_init() {
    g_min_enc = 0xFFFFFFFFu;  // encodes +inf side
    g_max_enc = 0x00000000u;  // encodes -inf side
}

// ---------------- kernel 1: global min/max of x ---------------------------
__global__ void k_minmax(const float* __restrict__ x, int n4) {
    const float4* x4 = (const float4*)x;
    int idx    = blockIdx.x * blockDim.x + threadIdx.x;
    int stride = gridDim.x * blockDim.x;
    float lmin =  3.402823466e38f;
    float lmax = -3.402823466e38f;
    for (int k = idx; k < n4; k += stride) {
        float4 v = x4[k];
        lmin = fminf(lmin, fminf(fminf(v.x, v.y), fminf(v.z, v.w)));
        lmax = fmaxf(lmax, fmaxf(fmaxf(v.x, v.y), fmaxf(v.z, v.w)));
    }
    #pragma unroll
    for (int off = 16; off; off >>= 1) {
        lmin = fminf(lmin, __shfl_xor_sync(0xffffffffu, lmin, off));
        lmax = fmaxf(lmax, __shfl_xor_sync(0xffffffffu, lmax, off));
    }
    __shared__ float smin[8], smax[8];
    int wid = threadIdx.x >> 5, lid = threadIdx.x & 31;
    if (lid == 0) { smin[wid] = lmin; smax[wid] = lmax; }
    __syncthreads();
    if (threadIdx.x == 0) {
        float m = smin[0], M = smax[0];
        #pragma unroll
        for (int w = 1; w < 8; w++) { m = fminf(m, smin[w]); M = fmaxf(M, smax[w]); }
        atomicMin(&g_min_enc, enc_f(m));
        atomicMax(&g_max_enc, enc_f(M));
    }
}

// ---------------- kernel 2: base_out = swish(x) @ W_base ------------------
// Block handles 16 batch rows x all 256 outputs. Thread = one output column,
// 16 accumulators, rank-1 updates over k with x staged (transposed) in smem.
__global__ __launch_bounds__(256) void k_base_gemm(const float* __restrict__ x,
                                                   const float* __restrict__ Wb) {
    __shared__ __align__(16) float sxT[IN_F][16];   // [k][b_local], 16 KiB
    const int b0  = blockIdx.x * 16;
    const int tid = threadIdx.x;

    // load x rows, apply swish, store transposed
    for (int idx = tid; idx < 16 * IN_F; idx += 256) {
        int bl = idx >> 8;            // idx / 256
        int k  = idx & (IN_F - 1);    // idx % 256   (coalesced global read)
        float v = x[(b0 + bl) * IN_F + k];
        float s = v / (1.0f + __expf(-v));
        sxT[k][bl] = s;
    }
    __syncthreads();

    float acc[16];
    #pragma unroll
    for (int i = 0; i < 16; i++) acc[i] = 0.0f;

    const int o = tid;
    #pragma unroll 4
    for (int k = 0; k < IN_F; k++) {
        float w = Wb[k * OUT_F + o];
        const float4* sr = (const float4*)&sxT[k][0];
        float4 s0 = sr[0], s1 = sr[1], s2 = sr[2], s3 = sr[3];
        acc[0]  += s0.x * w;  acc[1]  += s0.y * w;  acc[2]  += s0.z * w;  acc[3]  += s0.w * w;
        acc[4]  += s1.x * w;  acc[5]  += s1.y * w;  acc[6]  += s1.z * w;  acc[7]  += s1.w * w;
        acc[8]  += s2.x * w;  acc[9]  += s2.y * w;  acc[10] += s2.z * w;  acc[11] += s2.w * w;
        acc[12] += s3.x * w;  acc[13] += s3.y * w;  acc[14] += s3.z * w;  acc[15] += s3.w * w;
    }
    #pragma unroll
    for (int bl = 0; bl < 16; bl++)
        g_base[(b0 + bl) * OUT_F + o] = acc[bl];
}

// ---------------- kernel 3: main fused output ------------------------------
// Grid: (IN_F/IPB, BATCH/BPB). Block = 256 threads:
//   i_local = tid>>6 (4 input-feature channels per block)
//   oq      = tid&63 (one float4 of the output row: o = 4*oq)
// Each thread holds its 4x8 slice of cheb_weight in REGISTERS (loaded once),
// then streams 64 batch rows: 1 broadcast x-load, Chebyshev recurrence,
// 1 LDG.128 of base (L2 hit), 32 FMA, 1 STG.128.
#define IPB 4
#define BPB 64
__global__ __launch_bounds__(256, 2) void k_cheb_main(const float* __restrict__ x,
                                                      const float* __restrict__ Wc,
                                                      float* __restrict__ out) {
    const int tid = threadIdx.x;
    const int il  = tid >> 6;       // 0..3
    const int oq  = tid & 63;       // 0..63
    const int i   = blockIdx.x * IPB + il;
    const int b0  = blockIdx.y * BPB;

    // --- load this thread's 32 cheb weights into registers ---
    // memory layout: Wc[i][o][d], element e of the 32-float run = (o=4oq+(e>>3), d=e&7)
    const float4* wp = (const float4*)(Wc + (size_t)i * (OUT_F * DEG) + oq * 32);
    float wr[4][8];
    #pragma unroll
    for (int q = 0; q < 8; q++) {
        float4 v = wp[q];
        int j = q >> 1;
        int db = (q & 1) * 4;
        wr[j][db + 0] = v.x; wr[j][db + 1] = v.y;
        wr[j][db + 2] = v.z; wr[j][db + 3] = v.w;
    }

    const float xmin  = dec_f(g_min_enc);
    const float xmax  = dec_f(g_max_enc);
    const float scale = 2.0f / (xmax - xmin);

    const float4* basep = (const float4*)g_base;
    float4* outp = (float4*)out;

    #pragma unroll 2
    for (int bb = 0; bb < BPB; bb++) {
        const int b = b0 + bb;
        float xv = __ldg(&x[b * IN_F + i]);               // warp-broadcast
        float xs = (xv - xmin) * scale - 1.0f;
        float T[8];
        T[0] = 1.0f; T[1] = xs;
        float xs2 = xs + xs;
        #pragma unroll
        for (int d = 2; d < 8; d++) T[d] = xs2 * T[d - 1] - T[d - 2];

        float4 r = basep[b * (OUT_F / 4) + oq];           // L2/L1 hit
        #pragma unroll
        for (int d = 0; d < 8; d++) {
            r.x += T[d] * wr[0][d];
            r.y += T[d] * wr[1][d];
            r.z += T[d] * wr[2][d];
            r.w += T[d] * wr[3][d];
        }
        outp[(size_t)(b * IN_F + i) * (OUT_F / 4) + oq] = r;   // 512B/warp burst
    }
}

// ---------------- launch ----------------------------------------------------
extern "C" void kernel_launch(void* const* d_in, const int* in_sizes, int n_in,
                              void* d_out, int out_size) {
    (void)in_sizes; (void)n_in; (void)out_size;
    const float* x  = (const float*)d_in[0];   // (2048, 256)
    const float* Wb = (const float*)d_in[1];   // (256, 256)
    const float* Wc = (const float*)d_in[2];   // (256, 256, 8)
    float* out = (float*)d_out;                // (2048, 256, 256)

    k_init<<<1, 1>>>();
    k_minmax<<<128, 256>>>(x, (BATCH * IN_F) / 4);
    k_base_gemm<<<BATCH / 16, 256>>>(x, Wb);
    k_cheb_main<<<dim3(IN_F / IPB, BATCH / BPB), 256>>>(x, Wc, out);
}

// round 17
// speedup vs baseline: 1.0282x; 1.0079x over previous
#include <cuda_runtime.h>

#define BATCH 2048
#define IN_F  256
#define OUT_F 256
#define DEG   8

// ---------------- device scratch (no allocation allowed) ----------------
__device__ unsigned int g_min_enc;
__device__ unsigned int g_max_enc;
__device__ float g_base[BATCH * OUT_F];   // 2 MiB, L2-resident

// Monotonic float<->uint encoding for atomic min/max
__device__ __forceinline__ unsigned int enc_f(float f) {
    unsigned int i = __float_as_uint(f);
    return (i & 0x80000000u) ? ~i : (i | 0x80000000u);
}
__device__ __forceinline__ float dec_f(unsigned int u) {
    unsigned int i = (u & 0x80000000u) ? (u & 0x7fffffffu) : ~u;
    return __uint_as_float(i);
}

// ---------------- kernel 0: reset reduction state (determinism) ----------
__global__ void k_init() {
    g_min_enc = 0xFFFFFFFFu;  // encodes +inf side
    g_max_enc = 0x00000000u;  // encodes -inf side
}

// ---------------- kernel 1: global min/max of x ---------------------------
__global__ void k_minmax(const float* __restrict__ x, int n4) {
    const float4* x4 = (const float4*)x;
    int idx    = blockIdx.x * blockDim.x + threadIdx.x;
    int stride = gridDim.x * blockDim.x;
    float lmin =  3.402823466e38f;
    float lmax = -3.402823466e38f;
    for (int k = idx; k < n4; k += stride) {
        float4 v = x4[k];
        lmin = fminf(lmin, fminf(fminf(v.x, v.y), fminf(v.z, v.w)));
        lmax = fmaxf(lmax, fmaxf(fmaxf(v.x, v.y), fmaxf(v.z, v.w)));
    }
    #pragma unroll
    for (int off = 16; off; off >>= 1) {
        lmin = fminf(lmin, __shfl_xor_sync(0xffffffffu, lmin, off));
        lmax = fmaxf(lmax, __shfl_xor_sync(0xffffffffu, lmax, off));
    }
    __shared__ float smin[8], smax[8];
    int wid = threadIdx.x >> 5, lid = threadIdx.x & 31;
    if (lid == 0) { smin[wid] = lmin; smax[wid] = lmax; }
    __syncthreads();
    if (threadIdx.x == 0) {
        float m = smin[0], M = smax[0];
        #pragma unroll
        for (int w = 1; w < 8; w++) { m = fminf(m, smin[w]); M = fmaxf(M, smax[w]); }
        atomicMin(&g_min_enc, enc_f(m));
        atomicMax(&g_max_enc, enc_f(M));
    }
}

// ---------------- kernel 2: base_out = swish(x) @ W_base ------------------
// Block handles 16 batch rows x all 256 outputs. Thread = one output column,
// 16 accumulators, rank-1 updates over k with x staged (transposed) in smem.
__global__ __launch_bounds__(256) void k_base_gemm(const float* __restrict__ x,
                                                   const float* __restrict__ Wb) {
    __shared__ __align__(16) float sxT[IN_F][16];   // [k][b_local], 16 KiB
    const int b0  = blockIdx.x * 16;
    const int tid = threadIdx.x;

    // load x rows, apply swish, store transposed
    for (int idx = tid; idx < 16 * IN_F; idx += 256) {
        int bl = idx >> 8;            // idx / 256
        int k  = idx & (IN_F - 1);    // idx % 256   (coalesced global read)
        float v = x[(b0 + bl) * IN_F + k];
        float s = v / (1.0f + __expf(-v));
        sxT[k][bl] = s;
    }
    __syncthreads();

    float acc[16];
    #pragma unroll
    for (int i = 0; i < 16; i++) acc[i] = 0.0f;

    const int o = tid;
    #pragma unroll 4
    for (int k = 0; k < IN_F; k++) {
        float w = Wb[k * OUT_F + o];
        const float4* sr = (const float4*)&sxT[k][0];
        float4 s0 = sr[0], s1 = sr[1], s2 = sr[2], s3 = sr[3];
        acc[0]  += s0.x * w;  acc[1]  += s0.y * w;  acc[2]  += s0.z * w;  acc[3]  += s0.w * w;
        acc[4]  += s1.x * w;  acc[5]  += s1.y * w;  acc[6]  += s1.z * w;  acc[7]  += s1.w * w;
        acc[8]  += s2.x * w;  acc[9]  += s2.y * w;  acc[10] += s2.z * w;  acc[11] += s2.w * w;
        acc[12] += s3.x * w;  acc[13] += s3.y * w;  acc[14] += s3.z * w;  acc[15] += s3.w * w;
    }
    #pragma unroll
    for (int bl = 0; bl < 16; bl++)
        g_base[(b0 + bl) * OUT_F + o] = acc[bl];
}

// ---------------- kernel 3: main fused output ------------------------------
// Grid: (IN_F/IPB, BATCH/BPB). Block = 256 threads:
//   i_local = tid>>6 (4 input-feature channels per block)
//   oq      = tid&63 (one float4 of the output row: o = 4*oq)
// Each thread holds its 4x8 slice of cheb_weight in REGISTERS (loaded once),
// then streams 64 batch rows: 1 broadcast x-load, Chebyshev recurrence,
// 1 LDG.128 of base (L2 hit), 32 FMA, 1 STG.128.
#define IPB 4
#define BPB 64
__global__ __launch_bounds__(256, 2) void k_cheb_main(const float* __restrict__ x,
                                                      const float* __restrict__ Wc,
                                                      float* __restrict__ out) {
    const int tid = threadIdx.x;
    const int il  = tid >> 6;       // 0..3
    const int oq  = tid & 63;       // 0..63
    const int i   = blockIdx.x * IPB + il;
    const int b0  = blockIdx.y * BPB;

    // --- load this thread's 32 cheb weights into registers ---
    // memory layout: Wc[i][o][d], element e of the 32-float run = (o=4oq+(e>>3), d=e&7)
    const float4* wp = (const float4*)(Wc + (size_t)i * (OUT_F * DEG) + oq * 32);
    float wr[4][8];
    #pragma unroll
    for (int q = 0; q < 8; q++) {
        float4 v = wp[q];
        int j = q >> 1;
        int db = (q & 1) * 4;
        wr[j][db + 0] = v.x; wr[j][db + 1] = v.y;
        wr[j][db + 2] = v.z; wr[j][db + 3] = v.w;
    }

    const float xmin  = dec_f(g_min_enc);
    const float xmax  = dec_f(g_max_enc);
    const float scale = 2.0f / (xmax - xmin);

    const float4* basep = (const float4*)g_base;
    float4* outp = (float4*)out;

    #pragma unroll 2
    for (int bb = 0; bb < BPB; bb++) {
        const int b = b0 + bb;
        float xv = __ldg(&x[b * IN_F + i]);               // warp-broadcast
        float xs = (xv - xmin) * scale - 1.0f;
        float T[8];
        T[0] = 1.0f; T[1] = xs;
        float xs2 = xs + xs;
        #pragma unroll
        for (int d = 2; d < 8; d++) T[d] = xs2 * T[d - 1] - T[d - 2];

        float4 r = basep[b * (OUT_F / 4) + oq];           // L2/L1 hit
        #pragma unroll
        for (int d = 0; d < 8; d++) {
            r.x += T[d] * wr[0][d];
            r.y += T[d] * wr[1][d];
            r.z += T[d] * wr[2][d];
            r.w += T[d] * wr[3][d];
        }
        outp[(size_t)(b * IN_F + i) * (OUT_F / 4) + oq] = r;   // 512B/warp burst
    }
}

// ---------------- launch ----------------------------------------------------
extern "C" void kernel_launch(void* const* d_in, const int* in_sizes, int n_in,
                              void* d_out, int out_size) {
    (void)in_sizes; (void)n_in; (void)out_size;
    const float* x  = (const float*)d_in[0];   // (2048, 256)
    const float* Wb = (const float*)d_in[1];   // (256, 256)
    const float* Wc = (const float*)d_in[2];   // (256, 256, 8)
    float* out = (float*)d_out;                // (2048, 256, 256)

    k_init<<<1, 1>>>();
    k_minmax<<<128, 256>>>(x, (BATCH * IN_F) / 4);
    k_base_gemm<<<BATCH / 16, 256>>>(x, Wb);
    k_cheb_main<<<dim3(IN_F / IPB, BATCH / BPB), 256>>>(x, Wc, out);
}